// round 12
// baseline (speedup 1.0000x reference)
#include <cuda_runtime.h>
#include <cuda_bf16.h>

#define BB 128
#define NN 4096
#define SS 8
#define DD 64
#define NTOK (BB*NN)
#define NPART 16
#define TOKPB (NN/NPART)
#define CHUNK 64
#define NCHUNK (TOKPB/CHUNK)
#define NROW (BB*SS)

__device__ float g_x[NTOK*DD];
__device__ float g_prep[NPART*NROW*DD];
__device__ float g_denp[NPART*NROW];
__device__ float g_qk[NROW*DD];
__device__ float g_slots[NROW*DD];
__device__ float g_dent[NROW];

__device__ float g_vwT[64*64];
__device__ float g_wihT[64*192];
__device__ float g_whhT[64*192];
__device__ float g_w1T[64*128];
__device__ float g_w2T[128*64];
__device__ float g_qwT[64*64];

typedef unsigned long long u64;
__device__ __forceinline__ u64 pk2(float x, float y){
    u64 r; asm("mov.b64 %0,{%1,%2};" : "=l"(r) : "f"(x), "f"(y)); return r;
}
__device__ __forceinline__ void up2(u64 v, float &x, float &y){
    asm("mov.b64 {%0,%1},%2;" : "=f"(x), "=f"(y) : "l"(v));
}
__device__ __forceinline__ u64 ffma2(u64 a, u64 b, u64 c){
    u64 d; asm("fma.rn.f32x2 %0,%1,%2,%3;" : "=l"(d) : "l"(a), "l"(b), "l"(c)); return d;
}

// ---------------- weight transpose (once per call) ----------------
__global__ void k_tr(const float* __restrict__ vw, const float* __restrict__ wih,
                     const float* __restrict__ whh, const float* __restrict__ w1,
                     const float* __restrict__ w2,  const float* __restrict__ qw){
    int i = blockIdx.x*256 + threadIdx.x;
    if (i < 4096){
        g_vwT[(i&63)*64 + (i>>6)] = vw[i];
    } else if (i < 16384){
        int j = i - 4096;  g_wihT[(j&63)*192 + (j>>6)] = wih[j];
    } else if (i < 28672){
        int j = i - 16384; g_whhT[(j&63)*192 + (j>>6)] = whh[j];
    } else if (i < 36864){
        int j = i - 28672; g_w1T[(j&63)*128 + (j>>6)] = w1[j];
    } else if (i < 45056){
        int j = i - 36864; g_w2T[(j&127)*64 + (j>>7)] = w2[j];
    } else if (i < 49152){
        int j = i - 45056; g_qwT[(j&63)*64 + (j>>6)] = qw[j];
    }
}

// ---------------- x = LayerNorm(inputs), 8-token ILP batching --------------
__global__ void k_prep(const float* __restrict__ inp,
                       const float* __restrict__ nw,
                       const float* __restrict__ nb){
    int gw = (blockIdx.x*blockDim.x + threadIdx.x) >> 5;
    int lane = threadIdx.x & 31;
    int nwarp = (gridDim.x*blockDim.x) >> 5;
    float2 wv = ((const float2*)nw)[lane];
    float2 bv = ((const float2*)nb)[lane];
    for (int t0 = gw*8; t0 < NTOK; t0 += nwarp*8){
        float2 v[8];
        #pragma unroll
        for (int j = 0; j < 8; j++)
            v[j] = ((const float2*)inp)[(size_t)(t0+j)*32 + lane];
        float s[8], q[8];
        #pragma unroll
        for (int j = 0; j < 8; j++){
            s[j] = v[j].x + v[j].y;
            q[j] = v[j].x*v[j].x + v[j].y*v[j].y;
        }
        #pragma unroll
        for (int o = 16; o; o >>= 1){
            #pragma unroll
            for (int j = 0; j < 8; j++){
                s[j] += __shfl_xor_sync(~0u, s[j], o);
                q[j] += __shfl_xor_sync(~0u, q[j], o);
            }
        }
        #pragma unroll
        for (int j = 0; j < 8; j++){
            float m = s[j]*(1.f/64.f);
            float rs = rsqrtf(q[j]*(1.f/64.f) - m*m + 1e-5f);
            float2 o2;
            o2.x = (v[j].x-m)*rs*wv.x + bv.x;
            o2.y = (v[j].y-m)*rs*wv.y + bv.y;
            ((float2*)g_x)[(size_t)(t0+j)*32 + lane] = o2;
        }
    }
}

// ---------------- attention accumulation, grid (16 parts, 128 batch) -------
__global__ void __launch_bounds__(256, 3) k_attn(int fin, float* __restrict__ out_w){
    int p = blockIdx.x, b = blockIdx.y;
    int tid = threadIdx.x, lane = tid & 31, w = tid >> 5;
    __shared__ float xs[CHUNK][68];
    __shared__ u64  ws2[CHUNK][10];
    __shared__ float lgs[CHUNK][12];
    __shared__ u64  qq[16][16];

    {
        int i = tid >> 4, j = tid & 15;
        int s = 4*(j>>3) + ((j>>1)&3);
        int d0 = 4*i + 2*(j&1);
        qq[i][j] = ((const u64*)g_qk)[b*256 + s*32 + (d0>>1)];
    }

    u64 acc[SS]; float dsum[SS];
    #pragma unroll
    for (int s = 0; s < SS; s++){ acc[s] = 0ull; dsum[s] = 0.f; }

    int base = b*NN + p*TOKPB;
    for (int c = 0; c < NCHUNK; c++){
        u64 xr[8];
        const u64* src = (const u64*)(g_x + (size_t)(base + c*CHUNK + 8*w)*64);
        #pragma unroll
        for (int j = 0; j < 8; j++) xr[j] = src[j*32 + lane];
        #pragma unroll
        for (int j = 0; j < 8; j++) *(u64*)&xs[8*w + j][2*lane] = xr[j];
        __syncthreads();

        if (tid < 128){
            int t = tid & 63, g = tid >> 6;
            u64 la0 = 0, la1 = 0, la2 = 0, la3 = 0;
            #pragma unroll
            for (int i = 0; i < 16; i++){
                ulonglong2 xv = *(const ulonglong2*)&xs[t][4*i];
                const ulonglong2* qp = (const ulonglong2*)&qq[i][8*g];
                ulonglong2 q0 = qp[0], q1 = qp[1], q2 = qp[2], q3 = qp[3];
                la0 = ffma2(xv.x, q0.x, la0); la0 = ffma2(xv.y, q0.y, la0);
                la1 = ffma2(xv.x, q1.x, la1); la1 = ffma2(xv.y, q1.y, la1);
                la2 = ffma2(xv.x, q2.x, la2); la2 = ffma2(xv.y, q2.y, la2);
                la3 = ffma2(xv.x, q3.x, la3); la3 = ffma2(xv.y, q3.y, la3);
            }
            float a, bq, l0, l1, l2, l3;
            up2(la0, a, bq); l0 = a + bq;
            up2(la1, a, bq); l1 = a + bq;
            up2(la2, a, bq); l2 = a + bq;
            up2(la3, a, bq); l3 = a + bq;
            *(float4*)&lgs[t][4*g] = make_float4(l0, l1, l2, l3);
        }
        __syncthreads();

        if (tid < 64){
            int t = tid;
            float4 A = *(const float4*)&lgs[t][0];
            float4 Bq = *(const float4*)&lgs[t][4];
            float lg[SS] = {A.x, A.y, A.z, A.w, Bq.x, Bq.y, Bq.z, Bq.w};
            float mx = -1e30f;
            #pragma unroll
            for (int s = 0; s < SS; s++) mx = fmaxf(mx, lg[s]);
            float sum = 0.f;
            #pragma unroll
            for (int s = 0; s < SS; s++){ lg[s] = __expf(lg[s]-mx); sum += lg[s]; }
            float inv = 1.f/sum;
            #pragma unroll
            for (int s = 0; s < SS; s++){
                lg[s] = lg[s]*inv + 1e-8f;
                dsum[s] += lg[s];
            }
            #pragma unroll
            for (int k = 0; k < 4; k++){
                ulonglong2 pr;
                pr.x = pk2(lg[2*k],   lg[2*k]);
                pr.y = pk2(lg[2*k+1], lg[2*k+1]);
                *(ulonglong2*)&ws2[t][2*k] = pr;
            }
            if (fin){
                float4* dst = (float4*)(out_w + (size_t)(base + c*CHUNK + t)*SS);
                dst[0] = make_float4(lg[0], lg[1], lg[2], lg[3]);
                dst[1] = make_float4(lg[4], lg[5], lg[6], lg[7]);
            }
        }
        __syncthreads();

        #pragma unroll
        for (int j = 0; j < 8; j++){
            int n = 8*w + j;
            ulonglong2 w0 = *(const ulonglong2*)&ws2[n][0];
            ulonglong2 w1p = *(const ulonglong2*)&ws2[n][2];
            ulonglong2 w2p = *(const ulonglong2*)&ws2[n][4];
            ulonglong2 w3p = *(const ulonglong2*)&ws2[n][6];
            u64 xv = xr[j];
            acc[0] = ffma2(xv, w0.x,  acc[0]);
            acc[1] = ffma2(xv, w0.y,  acc[1]);
            acc[2] = ffma2(xv, w1p.x, acc[2]);
            acc[3] = ffma2(xv, w1p.y, acc[3]);
            acc[4] = ffma2(xv, w2p.x, acc[4]);
            acc[5] = ffma2(xv, w2p.y, acc[5]);
            acc[6] = ffma2(xv, w3p.x, acc[6]);
            acc[7] = ffma2(xv, w3p.y, acc[7]);
        }
    }
    __syncthreads();

    float* red  = &xs[0][0];
    float* dred = &lgs[0][0];
    #pragma unroll
    for (int s = 0; s < SS; s++){
        float a, bq; up2(acc[s], a, bq);
        red[w*512 + s*64 + 2*lane]   = a;
        red[w*512 + s*64 + 2*lane+1] = bq;
    }
    if (tid < 64){
        #pragma unroll
        for (int s = 0; s < SS; s++) dred[s*64 + tid] = dsum[s];
    }
    __syncthreads();
    #pragma unroll
    for (int k = 0; k < 2; k++){
        int o = tid + k*256;
        float sum = 0.f;
        #pragma unroll
        for (int ww = 0; ww < 8; ww++) sum += red[ww*512 + o];
        g_prep[p*NROW*DD + b*512 + o] = sum;
    }
    if (tid < 8){
        float sum = 0.f;
        #pragma unroll
        for (int t2 = 0; t2 < 64; t2++) sum += dred[tid*64 + t2];
        g_denp[p*NROW + b*SS + tid] = sum;
    }
}

// ---------------- slot update: 256 threads/row ----------------
__global__ void __launch_bounds__(256) k_update(int init, int wout,
    const float* __restrict__ eps, const float* __restrict__ mu,
    const float* __restrict__ lv,
    const float* __restrict__ bih, const float* __restrict__ bhh,
    const float* __restrict__ nrw, const float* __restrict__ nrb,
    const float* __restrict__ b2,  const float* __restrict__ nsw,
    const float* __restrict__ nsb, const float* __restrict__ kw,
    float* __restrict__ out_slots){
    int r = blockIdx.x;
    int tid = threadIdx.x, d = tid & 63, q = tid >> 6;
    int lane = tid & 31, w = tid >> 5;
    __shared__ float av[64], hp[64], tt[64], mm[128];
    __shared__ float pp[4][144];
    __shared__ float pg[6][4][64];
    __shared__ float ps[8], pq2[8];
    float h2;
    if (!init){
        float den = 0.f;
        #pragma unroll
        for (int p = 0; p < NPART; p++) den += g_denp[p*NROW + r];
        if (tid == 0 && wout) g_dent[r] = den;
        float pre = 0.f;
        #pragma unroll
        for (int p = 0; p < NPART; p++) pre += g_prep[p*NROW*DD + r*64 + d];
        if (q == 0){ av[d] = pre/den; hp[d] = g_slots[r*64 + d]; }
        __syncthreads();
        float at = 0.f;
        #pragma unroll
        for (int e0 = 0; e0 < 16; e0++){
            int e = q*16 + e0;
            at += av[e]*g_vwT[e*64 + d];
        }
        pp[q][d] = at;
        __syncthreads();
        at = (pp[0][d]+pp[1][d]) + (pp[2][d]+pp[3][d]);
        __syncthreads();
        if (q == 0) av[d] = at;
        __syncthreads();
        float gr=0.f, gz=0.f, gn=0.f, hr=0.f, hz=0.f, hn=0.f;
        #pragma unroll
        for (int e0 = 0; e0 < 16; e0++){
            int e = q*16 + e0;
            float a = av[e], hpe = hp[e];
            const float* wi = &g_wihT[e*192];
            const float* wh = &g_whhT[e*192];
            gr += a*wi[d];      gz += a*wi[64+d];
            gn += a*wi[128+d];  hr += hpe*wh[d];
            hz += hpe*wh[64+d]; hn += hpe*wh[128+d];
        }
        pg[0][q][d]=gr; pg[1][q][d]=gz; pg[2][q][d]=gn;
        pg[3][q][d]=hr; pg[4][q][d]=hz; pg[5][q][d]=hn;
        __syncthreads();
        gr = bih[d]; gz = bih[64+d]; gn = bih[128+d];
        hr = bhh[d]; hz = bhh[64+d]; hn = bhh[128+d];
        #pragma unroll
        for (int k = 0; k < 4; k++){
            gr += pg[0][k][d]; gz += pg[1][k][d]; gn += pg[2][k][d];
            hr += pg[3][k][d]; hz += pg[4][k][d]; hn += pg[5][k][d];
        }
        float rg = 1.f/(1.f + __expf(-(gr+hr)));
        float zg = 1.f/(1.f + __expf(-(gz+hz)));
        float ng = tanhf(gn + rg*hn);
        float h = (1.f-zg)*ng + zg*hp[d];
        float s = h, qs = h*h;
        #pragma unroll
        for (int o = 16; o; o >>= 1){
            s  += __shfl_xor_sync(~0u, s,  o);
            qs += __shfl_xor_sync(~0u, qs, o);
        }
        if (lane == 0){ ps[w] = s; pq2[w] = qs; }
        __syncthreads();
        int wb = w & ~1;
        s = ps[wb] + ps[wb+1]; qs = pq2[wb] + pq2[wb+1];
        float m = s*(1.f/64.f);
        float rs = rsqrtf(qs*(1.f/64.f) - m*m + 1e-5f);
        float ttv = (h-m)*rs*nrw[d] + nrb[d];
        __syncthreads();
        if (q == 0) tt[d] = ttv;
        __syncthreads();
        int j = tid & 127, hq = tid >> 7;
        float m1 = 0.f;
        #pragma unroll
        for (int e0 = 0; e0 < 32; e0++){
            int e = hq*32 + e0;
            m1 += tt[e]*g_w1T[e*128 + j];
        }
        pp[hq][j] = m1;
        __syncthreads();
        if (hq == 0) mm[j] = fmaxf(pp[0][j] + pp[1][j], 0.f);
        __syncthreads();
        float o2 = 0.f;
        #pragma unroll
        for (int j0 = 0; j0 < 32; j0++){
            int jj = q*32 + j0;
            o2 += mm[jj]*g_w2T[jj*64 + d];
        }
        pp[q][d] = o2;
        __syncthreads();
        h2 = h + b2[d] + (pp[0][d]+pp[1][d]) + (pp[2][d]+pp[3][d]);
        __syncthreads();
    } else {
        h2 = mu[d] + __expf(0.5f*lv[d])*eps[r*64 + d];
    }
    if (q == 0){
        g_slots[r*64 + d] = h2;
        if (wout) out_slots[r*64 + d] = h2;
    }
    float s2 = h2, q2s = h2*h2;
    #pragma unroll
    for (int o = 16; o; o >>= 1){
        s2  += __shfl_xor_sync(~0u, s2,  o);
        q2s += __shfl_xor_sync(~0u, q2s, o);
    }
    if (lane == 0){ ps[w] = s2; pq2[w] = q2s; }
    __syncthreads();
    int wb2 = w & ~1;
    s2 = ps[wb2] + ps[wb2+1]; q2s = pq2[wb2] + pq2[wb2+1];
    float m2 = s2*(1.f/64.f);
    float rs2 = rsqrtf(q2s*(1.f/64.f) - m2*m2 + 1e-5f);
    float ttv2 = (h2-m2)*rs2*nsw[d] + nsb[d];
    __syncthreads();
    if (q == 0) tt[d] = ttv2;
    __syncthreads();
    float qd = 0.f;
    #pragma unroll
    for (int e0 = 0; e0 < 16; e0++){
        int e = q*16 + e0;
        qd += tt[e]*g_qwT[e*64 + d];
    }
    pp[q][d] = qd;
    __syncthreads();
    float qv = (pp[0][d]+pp[1][d]) + (pp[2][d]+pp[3][d]);
    __syncthreads();
    if (q == 0) av[d] = qv;
    __syncthreads();
    float qk = 0.f;
    #pragma unroll
    for (int e0 = 0; e0 < 16; e0++){
        int e = q*16 + e0;
        qk += av[e]*kw[e*64 + d];
    }
    pp[q][d] = qk;
    __syncthreads();
    if (q == 0)
        g_qk[r*64 + d] = 0.125f*((pp[0][d]+pp[1][d]) + (pp[2][d]+pp[3][d]));
}

// ---------------- w = what / denom ----------------
__global__ void __launch_bounds__(256) k_wnorm(float* __restrict__ out_w){
    __shared__ float invd[8];
    int tok = blockIdx.x*256 + threadIdx.x;
    int b = tok >> 12;
    if (threadIdx.x < 8) invd[threadIdx.x] = 1.f/g_dent[b*SS + threadIdx.x];
    __syncthreads();
    float4* pw = (float4*)(out_w + (size_t)tok*SS);
    float4 a = pw[0], c = pw[1];
    a.x *= invd[0]; a.y *= invd[1]; a.z *= invd[2]; a.w *= invd[3];
    c.x *= invd[4]; c.y *= invd[5]; c.z *= invd[6]; c.w *= invd[7];
    pw[0] = a; pw[1] = c;
}

extern "C" void kernel_launch(void* const* d_in, const int* in_sizes, int n_in,
                              void* d_out, int out_size){
    const float* inp = (const float*)d_in[0];
    const float* eps = (const float*)d_in[1];
    const float* mu  = (const float*)d_in[2];
    const float* lv  = (const float*)d_in[3];
    const float* kw  = (const float*)d_in[4];
    const float* vw  = (const float*)d_in[5];
    const float* qw  = (const float*)d_in[6];
    const float* niw = (const float*)d_in[7];
    const float* nib = (const float*)d_in[8];
    const float* nsw = (const float*)d_in[9];
    const float* nsb = (const float*)d_in[10];
    const float* nrw = (const float*)d_in[11];
    const float* nrb = (const float*)d_in[12];
    const float* wih = (const float*)d_in[13];
    const float* whh = (const float*)d_in[14];
    const float* bih = (const float*)d_in[15];
    const float* bhh = (const float*)d_in[16];
    const float* w1  = (const float*)d_in[17];
    const float* w2  = (const float*)d_in[18];
    const float* b2  = (const float*)d_in[19];
    float* out_slots = (float*)d_out;
    float* out_w     = out_slots + NROW*DD;

    k_tr<<<192, 256>>>(vw, wih, whh, w1, w2, qw);
    k_prep<<<2048, 256>>>(inp, niw, nib);
    k_update<<<NROW, 256>>>(1, 0, eps, mu, lv, bih, bhh,
                            nrw, nrb, b2, nsw, nsb, kw, out_slots);
    for (int step = 0; step < 4; step++){
        int fin = (step == 3);
        k_attn<<<dim3(NPART, BB), 256>>>(fin, out_w);
        k_update<<<NROW, 256>>>(0, fin, eps, mu, lv, bih, bhh,
                                nrw, nrb, b2, nsw, nsb, kw, out_slots);
    }
    k_wnorm<<<NTOK/256, 256>>>(out_w);
}

// round 13
// speedup vs baseline: 1.3475x; 1.3475x over previous
#include <cuda_runtime.h>
#include <cuda_bf16.h>

#define BB 128
#define NN 4096
#define SS 8
#define DD 64
#define NTOK (BB*NN)
#define NPART 16
#define TOKPB (NN/NPART)
#define CHUNK 64
#define NCHUNK (TOKPB/CHUNK)
#define NROW (BB*SS)

__device__ float g_x[NTOK*DD];
__device__ float g_prep[NPART*NROW*DD];
__device__ float g_denp[NPART*NROW];
__device__ float g_qk[NROW*DD];
__device__ float g_slots[NROW*DD];
__device__ float g_dent[NROW];
__device__ int   g_ctr[4*BB];

__device__ float g_vwT[64*64];
__device__ float g_wihT[64*192];
__device__ float g_whhT[64*192];
__device__ float g_w1T[64*128];
__device__ float g_w2T[128*64];
__device__ float g_qwT[64*64];

typedef unsigned long long u64;
__device__ __forceinline__ u64 pk2(float x, float y){
    u64 r; asm("mov.b64 %0,{%1,%2};" : "=l"(r) : "f"(x), "f"(y)); return r;
}
__device__ __forceinline__ void up2(u64 v, float &x, float &y){
    asm("mov.b64 {%0,%1},%2;" : "=f"(x), "=f"(y) : "l"(v));
}
__device__ __forceinline__ u64 ffma2(u64 a, u64 b, u64 c){
    u64 d; asm("fma.rn.f32x2 %0,%1,%2,%3;" : "=l"(d) : "l"(a), "l"(b), "l"(c)); return d;
}

// ---------------- weight transpose + counter reset (once per call) ---------
__global__ void k_tr(const float* __restrict__ vw, const float* __restrict__ wih,
                     const float* __restrict__ whh, const float* __restrict__ w1,
                     const float* __restrict__ w2,  const float* __restrict__ qw){
    int i = blockIdx.x*256 + threadIdx.x;
    if (i < 4*BB) g_ctr[i] = 0;
    if (i < 4096){
        g_vwT[(i&63)*64 + (i>>6)] = vw[i];
    } else if (i < 16384){
        int j = i - 4096;  g_wihT[(j&63)*192 + (j>>6)] = wih[j];
    } else if (i < 28672){
        int j = i - 16384; g_whhT[(j&63)*192 + (j>>6)] = whh[j];
    } else if (i < 36864){
        int j = i - 28672; g_w1T[(j&63)*128 + (j>>6)] = w1[j];
    } else if (i < 45056){
        int j = i - 36864; g_w2T[(j&127)*64 + (j>>7)] = w2[j];
    } else if (i < 49152){
        int j = i - 45056; g_qwT[(j&63)*64 + (j>>6)] = qw[j];
    }
}

// ---------------- x = LayerNorm(inputs)  (R11 version) ----------------
__global__ void k_prep(const float* __restrict__ inp,
                       const float* __restrict__ nw,
                       const float* __restrict__ nb){
    int gw = (blockIdx.x*blockDim.x + threadIdx.x) >> 5;
    int lane = threadIdx.x & 31;
    int nwarp = (gridDim.x*blockDim.x) >> 5;
    float2 wv = ((const float2*)nw)[lane];
    float2 bv = ((const float2*)nb)[lane];
    for (int t = gw; t < NTOK; t += nwarp){
        float2 v = ((const float2*)inp)[(size_t)t*32 + lane];
        float s = v.x + v.y, q = v.x*v.x + v.y*v.y;
        #pragma unroll
        for (int o = 16; o; o >>= 1){
            s += __shfl_xor_sync(~0u, s, o);
            q += __shfl_xor_sync(~0u, q, o);
        }
        float m = s*(1.f/64.f);
        float rs = rsqrtf(q*(1.f/64.f) - m*m + 1e-5f);
        float2 o2;
        o2.x = (v.x-m)*rs*wv.x + bv.x;
        o2.y = (v.y-m)*rs*wv.y + bv.y;
        ((float2*)g_x)[(size_t)t*32 + lane] = o2;
    }
}

// ---------------- attention + fused tail slot-update -----------------------
// main body identical to R11; after the partition epilogue, the last of the
// 16 partition blocks per batch runs the GRU/MLP update + next-qk for the
// batch's 8 rows (one warp per row; warp-local exchanges only).
__global__ void __launch_bounds__(256, 3) k_attn(int step, float* __restrict__ out_w,
    const float* __restrict__ bih, const float* __restrict__ bhh,
    const float* __restrict__ nrw, const float* __restrict__ nrb,
    const float* __restrict__ b2,  const float* __restrict__ nsw,
    const float* __restrict__ nsb, const float* __restrict__ kw,
    float* __restrict__ out_slots){
    int fin = (step == 3);
    int p = blockIdx.x, b = blockIdx.y;
    int tid = threadIdx.x, lane = tid & 31, w = tid >> 5;
    __shared__ float xs[CHUNK][68];
    __shared__ u64  ws2[CHUNK][10];
    __shared__ float lgs[CHUNK][12];
    __shared__ u64  qq[16][16];
    __shared__ float t_av[8][64], t_hp[8][64], t_tt[8][64], t_mm[8][128];
    __shared__ int lastFlag;

    {
        int i = tid >> 4, j = tid & 15;
        int s = 4*(j>>3) + ((j>>1)&3);
        int d0 = 4*i + 2*(j&1);
        qq[i][j] = ((const u64*)g_qk)[b*256 + s*32 + (d0>>1)];
    }

    u64 acc[SS]; float dsum[SS];
    #pragma unroll
    for (int s = 0; s < SS; s++){ acc[s] = 0ull; dsum[s] = 0.f; }

    int base = b*NN + p*TOKPB;
    for (int c = 0; c < NCHUNK; c++){
        u64 xr[8];
        const u64* src = (const u64*)(g_x + (size_t)(base + c*CHUNK + 8*w)*64);
        #pragma unroll
        for (int j = 0; j < 8; j++) xr[j] = src[j*32 + lane];
        #pragma unroll
        for (int j = 0; j < 8; j++) *(u64*)&xs[8*w + j][2*lane] = xr[j];
        __syncthreads();

        if (tid < 128){
            int t = tid & 63, g = tid >> 6;
            u64 la0 = 0, la1 = 0, la2 = 0, la3 = 0;
            #pragma unroll
            for (int i = 0; i < 16; i++){
                ulonglong2 xv = *(const ulonglong2*)&xs[t][4*i];
                const ulonglong2* qp = (const ulonglong2*)&qq[i][8*g];
                ulonglong2 q0 = qp[0], q1 = qp[1], q2 = qp[2], q3 = qp[3];
                la0 = ffma2(xv.x, q0.x, la0); la0 = ffma2(xv.y, q0.y, la0);
                la1 = ffma2(xv.x, q1.x, la1); la1 = ffma2(xv.y, q1.y, la1);
                la2 = ffma2(xv.x, q2.x, la2); la2 = ffma2(xv.y, q2.y, la2);
                la3 = ffma2(xv.x, q3.x, la3); la3 = ffma2(xv.y, q3.y, la3);
            }
            float a, bq, l0, l1, l2, l3;
            up2(la0, a, bq); l0 = a + bq;
            up2(la1, a, bq); l1 = a + bq;
            up2(la2, a, bq); l2 = a + bq;
            up2(la3, a, bq); l3 = a + bq;
            *(float4*)&lgs[t][4*g] = make_float4(l0, l1, l2, l3);
        }
        __syncthreads();

        if (tid < 64){
            int t = tid;
            float4 A = *(const float4*)&lgs[t][0];
            float4 Bq = *(const float4*)&lgs[t][4];
            float lg[SS] = {A.x, A.y, A.z, A.w, Bq.x, Bq.y, Bq.z, Bq.w};
            float mx = -1e30f;
            #pragma unroll
            for (int s = 0; s < SS; s++) mx = fmaxf(mx, lg[s]);
            float sum = 0.f;
            #pragma unroll
            for (int s = 0; s < SS; s++){ lg[s] = __expf(lg[s]-mx); sum += lg[s]; }
            float inv = 1.f/sum;
            #pragma unroll
            for (int s = 0; s < SS; s++){
                lg[s] = lg[s]*inv + 1e-8f;
                dsum[s] += lg[s];
            }
            #pragma unroll
            for (int k = 0; k < 4; k++){
                ulonglong2 pr;
                pr.x = pk2(lg[2*k],   lg[2*k]);
                pr.y = pk2(lg[2*k+1], lg[2*k+1]);
                *(ulonglong2*)&ws2[t][2*k] = pr;
            }
            if (fin){
                float4* dst = (float4*)(out_w + (size_t)(base + c*CHUNK + t)*SS);
                dst[0] = make_float4(lg[0], lg[1], lg[2], lg[3]);
                dst[1] = make_float4(lg[4], lg[5], lg[6], lg[7]);
            }
        }
        __syncthreads();

        #pragma unroll
        for (int j = 0; j < 8; j++){
            int n = 8*w + j;
            ulonglong2 w0 = *(const ulonglong2*)&ws2[n][0];
            ulonglong2 w1p = *(const ulonglong2*)&ws2[n][2];
            ulonglong2 w2p = *(const ulonglong2*)&ws2[n][4];
            ulonglong2 w3p = *(const ulonglong2*)&ws2[n][6];
            u64 xv = xr[j];
            acc[0] = ffma2(xv, w0.x,  acc[0]);
            acc[1] = ffma2(xv, w0.y,  acc[1]);
            acc[2] = ffma2(xv, w1p.x, acc[2]);
            acc[3] = ffma2(xv, w1p.y, acc[3]);
            acc[4] = ffma2(xv, w2p.x, acc[4]);
            acc[5] = ffma2(xv, w2p.y, acc[5]);
            acc[6] = ffma2(xv, w3p.x, acc[6]);
            acc[7] = ffma2(xv, w3p.y, acc[7]);
        }
    }
    __syncthreads();

    float* red  = &xs[0][0];
    float* dred = &lgs[0][0];
    #pragma unroll
    for (int s = 0; s < SS; s++){
        float a, bq; up2(acc[s], a, bq);
        red[w*512 + s*64 + 2*lane]   = a;
        red[w*512 + s*64 + 2*lane+1] = bq;
    }
    if (tid < 64){
        #pragma unroll
        for (int s = 0; s < SS; s++) dred[s*64 + tid] = dsum[s];
    }
    __syncthreads();
    #pragma unroll
    for (int k = 0; k < 2; k++){
        int o = tid + k*256;
        float sum = 0.f;
        #pragma unroll
        for (int ww = 0; ww < 8; ww++) sum += red[ww*512 + o];
        g_prep[p*NROW*DD + b*512 + o] = sum;
    }
    if (tid < 8){
        float sum = 0.f;
        #pragma unroll
        for (int t2 = 0; t2 < 64; t2++) sum += dred[tid*64 + t2];
        g_denp[p*NROW + b*SS + tid] = sum;
    }

    // ---- last-block-done tail: slot update for this batch ----
    __threadfence();
    if (tid == 0){
        int old = atomicAdd(&g_ctr[step*BB + b], 1);
        lastFlag = (old == NPART-1) ? 1 : 0;
    }
    __syncthreads();
    if (!lastFlag) return;
    __threadfence();

    int rr = tid >> 5, l = tid & 31;
    int r = b*SS + rr;
    int d0 = l, d1 = l + 32;

    float den = 0.f;
    #pragma unroll
    for (int p2 = 0; p2 < NPART; p2++) den += g_denp[p2*NROW + r];
    if (fin && l == 0) g_dent[r] = den;
    float pre0 = 0.f, pre1 = 0.f;
    #pragma unroll
    for (int p2 = 0; p2 < NPART; p2++){
        const float* gp = &g_prep[(size_t)p2*NROW*DD + r*64];
        pre0 += gp[d0]; pre1 += gp[d1];
    }
    t_av[rr][d0] = pre0/den; t_av[rr][d1] = pre1/den;
    float hp0 = g_slots[r*64 + d0], hp1 = g_slots[r*64 + d1];
    t_hp[rr][d0] = hp0; t_hp[rr][d1] = hp1;
    __syncwarp();
    float at0 = 0.f, at1 = 0.f;
    #pragma unroll 8
    for (int e = 0; e < 64; e++){
        float a = t_av[rr][e];
        at0 += a*g_vwT[e*64 + d0];
        at1 += a*g_vwT[e*64 + d1];
    }
    __syncwarp();
    t_av[rr][d0] = at0; t_av[rr][d1] = at1;
    __syncwarp();
    float gr0=bih[d0], gz0=bih[64+d0], gn0=bih[128+d0];
    float hr0=bhh[d0], hz0=bhh[64+d0], hn0=bhh[128+d0];
    float gr1=bih[d1], gz1=bih[64+d1], gn1=bih[128+d1];
    float hr1=bhh[d1], hz1=bhh[64+d1], hn1=bhh[128+d1];
    #pragma unroll 4
    for (int e = 0; e < 64; e++){
        float a = t_av[rr][e], hpe = t_hp[rr][e];
        const float* wi = &g_wihT[e*192];
        const float* wh = &g_whhT[e*192];
        gr0 += a*wi[d0];   gz0 += a*wi[64+d0];   gn0 += a*wi[128+d0];
        hr0 += hpe*wh[d0]; hz0 += hpe*wh[64+d0]; hn0 += hpe*wh[128+d0];
        gr1 += a*wi[d1];   gz1 += a*wi[64+d1];   gn1 += a*wi[128+d1];
        hr1 += hpe*wh[d1]; hz1 += hpe*wh[64+d1]; hn1 += hpe*wh[128+d1];
    }
    float rg0 = 1.f/(1.f + __expf(-(gr0+hr0)));
    float zg0 = 1.f/(1.f + __expf(-(gz0+hz0)));
    float ng0 = tanhf(gn0 + rg0*hn0);
    float h0 = (1.f-zg0)*ng0 + zg0*hp0;
    float rg1 = 1.f/(1.f + __expf(-(gr1+hr1)));
    float zg1 = 1.f/(1.f + __expf(-(gz1+hz1)));
    float ng1 = tanhf(gn1 + rg1*hn1);
    float h1 = (1.f-zg1)*ng1 + zg1*hp1;
    // LN(h, nr) via warp reduce over the row's 64 values
    float s = h0 + h1, qsum = h0*h0 + h1*h1;
    #pragma unroll
    for (int o = 16; o; o >>= 1){
        s    += __shfl_xor_sync(~0u, s,    o);
        qsum += __shfl_xor_sync(~0u, qsum, o);
    }
    float m = s*(1.f/64.f);
    float rs = rsqrtf(qsum*(1.f/64.f) - m*m + 1e-5f);
    t_tt[rr][d0] = (h0-m)*rs*nrw[d0] + nrb[d0];
    t_tt[rr][d1] = (h1-m)*rs*nrw[d1] + nrb[d1];
    __syncwarp();
    float m0=0.f, m1=0.f, m2v=0.f, m3=0.f;
    #pragma unroll 8
    for (int e = 0; e < 64; e++){
        float t = t_tt[rr][e];
        const float* w1r = &g_w1T[e*128];
        m0  += t*w1r[l];
        m1  += t*w1r[l+32];
        m2v += t*w1r[l+64];
        m3  += t*w1r[l+96];
    }
    t_mm[rr][l]    = fmaxf(m0, 0.f);
    t_mm[rr][l+32] = fmaxf(m1, 0.f);
    t_mm[rr][l+64] = fmaxf(m2v, 0.f);
    t_mm[rr][l+96] = fmaxf(m3, 0.f);
    __syncwarp();
    float o0 = h0 + b2[d0], o1 = h1 + b2[d1];
    #pragma unroll 8
    for (int j = 0; j < 128; j++){
        float mv = t_mm[rr][j];
        o0 += mv*g_w2T[j*64 + d0];
        o1 += mv*g_w2T[j*64 + d1];
    }
    g_slots[r*64 + d0] = o0; g_slots[r*64 + d1] = o1;
    if (fin){
        out_slots[r*64 + d0] = o0; out_slots[r*64 + d1] = o1;
        return;
    }
    // next qk = (LN(h2,ns)@qw^T)@kw / 8
    float s2 = o0 + o1, q2s = o0*o0 + o1*o1;
    #pragma unroll
    for (int o = 16; o; o >>= 1){
        s2  += __shfl_xor_sync(~0u, s2,  o);
        q2s += __shfl_xor_sync(~0u, q2s, o);
    }
    float m2 = s2*(1.f/64.f);
    float rs2 = rsqrtf(q2s*(1.f/64.f) - m2*m2 + 1e-5f);
    t_tt[rr][d0] = (o0-m2)*rs2*nsw[d0] + nsb[d0];
    t_tt[rr][d1] = (o1-m2)*rs2*nsw[d1] + nsb[d1];
    __syncwarp();
    float qd0 = 0.f, qd1 = 0.f;
    #pragma unroll 8
    for (int e = 0; e < 64; e++){
        float t = t_tt[rr][e];
        qd0 += t*g_qwT[e*64 + d0];
        qd1 += t*g_qwT[e*64 + d1];
    }
    __syncwarp();
    t_av[rr][d0] = qd0; t_av[rr][d1] = qd1;
    __syncwarp();
    float qk0 = 0.f, qk1 = 0.f;
    #pragma unroll 8
    for (int e = 0; e < 64; e++){
        float a = t_av[rr][e];
        qk0 += a*kw[e*64 + d0];
        qk1 += a*kw[e*64 + d1];
    }
    g_qk[r*64 + d0] = 0.125f*qk0;
    g_qk[r*64 + d1] = 0.125f*qk1;
}

// ---------------- slot init (eps/mu/lv) + first qk -------------------------
__global__ void __launch_bounds__(256) k_init(
    const float* __restrict__ eps, const float* __restrict__ mu,
    const float* __restrict__ lv,  const float* __restrict__ nsw,
    const float* __restrict__ nsb, const float* __restrict__ kw){
    int r = blockIdx.x;
    int tid = threadIdx.x, d = tid & 63, q = tid >> 6;
    int lane = tid & 31, w = tid >> 5;
    __shared__ float av[64], tt[64];
    __shared__ float pp[4][144];
    __shared__ float ps[8], pq2[8];
    float h2 = mu[d] + __expf(0.5f*lv[d])*eps[r*64 + d];
    if (q == 0) g_slots[r*64 + d] = h2;
    float s2 = h2, q2s = h2*h2;
    #pragma unroll
    for (int o = 16; o; o >>= 1){
        s2  += __shfl_xor_sync(~0u, s2,  o);
        q2s += __shfl_xor_sync(~0u, q2s, o);
    }
    if (lane == 0){ ps[w] = s2; pq2[w] = q2s; }
    __syncthreads();
    int wb2 = w & ~1;
    s2 = ps[wb2] + ps[wb2+1]; q2s = pq2[wb2] + pq2[wb2+1];
    float m2 = s2*(1.f/64.f);
    float rs2 = rsqrtf(q2s*(1.f/64.f) - m2*m2 + 1e-5f);
    float ttv2 = (h2-m2)*rs2*nsw[d] + nsb[d];
    __syncthreads();
    if (q == 0) tt[d] = ttv2;
    __syncthreads();
    float qd = 0.f;
    #pragma unroll
    for (int e0 = 0; e0 < 16; e0++){
        int e = q*16 + e0;
        qd += tt[e]*g_qwT[e*64 + d];
    }
    pp[q][d] = qd;
    __syncthreads();
    float qv = (pp[0][d]+pp[1][d]) + (pp[2][d]+pp[3][d]);
    __syncthreads();
    if (q == 0) av[d] = qv;
    __syncthreads();
    float qk = 0.f;
    #pragma unroll
    for (int e0 = 0; e0 < 16; e0++){
        int e = q*16 + e0;
        qk += av[e]*kw[e*64 + d];
    }
    pp[q][d] = qk;
    __syncthreads();
    if (q == 0)
        g_qk[r*64 + d] = 0.125f*((pp[0][d]+pp[1][d]) + (pp[2][d]+pp[3][d]));
}

// ---------------- w = what / denom ----------------
__global__ void __launch_bounds__(256) k_wnorm(float* __restrict__ out_w){
    __shared__ float invd[8];
    int tok = blockIdx.x*256 + threadIdx.x;
    int b = tok >> 12;
    if (threadIdx.x < 8) invd[threadIdx.x] = 1.f/g_dent[b*SS + threadIdx.x];
    __syncthreads();
    float4* pw = (float4*)(out_w + (size_t)tok*SS);
    float4 a = pw[0], c = pw[1];
    a.x *= invd[0]; a.y *= invd[1]; a.z *= invd[2]; a.w *= invd[3];
    c.x *= invd[4]; c.y *= invd[5]; c.z *= invd[6]; c.w *= invd[7];
    pw[0] = a; pw[1] = c;
}

extern "C" void kernel_launch(void* const* d_in, const int* in_sizes, int n_in,
                              void* d_out, int out_size){
    const float* inp = (const float*)d_in[0];
    const float* eps = (const float*)d_in[1];
    const float* mu  = (const float*)d_in[2];
    const float* lv  = (const float*)d_in[3];
    const float* kw  = (const float*)d_in[4];
    const float* vw  = (const float*)d_in[5];
    const float* qw  = (const float*)d_in[6];
    const float* niw = (const float*)d_in[7];
    const float* nib = (const float*)d_in[8];
    const float* nsw = (const float*)d_in[9];
    const float* nsb = (const float*)d_in[10];
    const float* nrw = (const float*)d_in[11];
    const float* nrb = (const float*)d_in[12];
    const float* bih = (const float*)d_in[15];
    const float* bhh = (const float*)d_in[16];
    const float* w1  = (const float*)d_in[17];
    const float* w2  = (const float*)d_in[18];
    const float* b2  = (const float*)d_in[19];
    const float* wih = (const float*)d_in[13];
    const float* whh = (const float*)d_in[14];
    float* out_slots = (float*)d_out;
    float* out_w     = out_slots + NROW*DD;

    k_tr<<<192, 256>>>(vw, wih, whh, w1, w2, qw);
    k_prep<<<2048, 256>>>(inp, niw, nib);
    k_init<<<NROW, 256>>>(eps, mu, lv, nsw, nsb, kw);
    for (int step = 0; step < 4; step++){
        k_attn<<<dim3(NPART, BB), 256>>>(step, out_w, bih, bhh,
                                         nrw, nrb, b2, nsw, nsb, kw, out_slots);
    }
    k_wnorm<<<NTOK/256, 256>>>(out_w);
}

// round 14
// speedup vs baseline: 1.4666x; 1.0883x over previous
#include <cuda_runtime.h>
#include <cuda_bf16.h>

#define BB 128
#define NN 4096
#define SS 8
#define DD 64
#define NTOK (BB*NN)
#define NPART 16
#define TOKPB (NN/NPART)
#define CHUNK 64
#define NCHUNK (TOKPB/CHUNK)
#define NROW (BB*SS)

__device__ float g_x[NTOK*DD];
__device__ float g_prep[NPART*NROW*DD];
__device__ float g_denp[NPART*NROW];
__device__ float g_qk[NROW*DD];
__device__ float g_slots[NROW*DD];
__device__ float g_dent[NROW];

__device__ float g_vwT[64*64];
__device__ float g_wihT[64*192];
__device__ float g_whhT[64*192];
__device__ float g_w1T[64*128];
__device__ float g_w2T[128*64];
__device__ float g_qwT[64*64];

typedef unsigned long long u64;
__device__ __forceinline__ u64 pk2(float x, float y){
    u64 r; asm("mov.b64 %0,{%1,%2};" : "=l"(r) : "f"(x), "f"(y)); return r;
}
__device__ __forceinline__ void up2(u64 v, float &x, float &y){
    asm("mov.b64 {%0,%1},%2;" : "=f"(x), "=f"(y) : "l"(v));
}
__device__ __forceinline__ u64 ffma2(u64 a, u64 b, u64 c){
    u64 d; asm("fma.rn.f32x2 %0,%1,%2,%3;" : "=l"(d) : "l"(a), "l"(b), "l"(c)); return d;
}

// ---------------- weight transpose (once per call) ----------------
__global__ void k_tr(const float* __restrict__ vw, const float* __restrict__ wih,
                     const float* __restrict__ whh, const float* __restrict__ w1,
                     const float* __restrict__ w2,  const float* __restrict__ qw){
    int i = blockIdx.x*256 + threadIdx.x;
    if (i < 4096){
        g_vwT[(i&63)*64 + (i>>6)] = vw[i];
    } else if (i < 16384){
        int j = i - 4096;  g_wihT[(j&63)*192 + (j>>6)] = wih[j];
    } else if (i < 28672){
        int j = i - 16384; g_whhT[(j&63)*192 + (j>>6)] = whh[j];
    } else if (i < 36864){
        int j = i - 28672; g_w1T[(j&63)*128 + (j>>6)] = w1[j];
    } else if (i < 45056){
        int j = i - 36864; g_w2T[(j&127)*64 + (j>>7)] = w2[j];
    } else if (i < 49152){
        int j = i - 45056; g_qwT[(j&63)*64 + (j>>6)] = qw[j];
    }
}

// ---------------- x = LayerNorm(inputs), 4-token ILP batching --------------
__global__ void k_prep(const float* __restrict__ inp,
                       const float* __restrict__ nw,
                       const float* __restrict__ nb){
    int gw = (blockIdx.x*blockDim.x + threadIdx.x) >> 5;
    int lane = threadIdx.x & 31;
    int nwarp = (gridDim.x*blockDim.x) >> 5;
    float2 wv = ((const float2*)nw)[lane];
    float2 bv = ((const float2*)nb)[lane];
    for (int t0 = gw*4; t0 < NTOK; t0 += nwarp*4){
        float2 v[4];
        #pragma unroll
        for (int j = 0; j < 4; j++)
            v[j] = ((const float2*)inp)[(size_t)(t0+j)*32 + lane];
        float s[4], q[4];
        #pragma unroll
        for (int j = 0; j < 4; j++){
            s[j] = v[j].x + v[j].y;
            q[j] = v[j].x*v[j].x + v[j].y*v[j].y;
        }
        #pragma unroll
        for (int o = 16; o; o >>= 1){
            #pragma unroll
            for (int j = 0; j < 4; j++){
                s[j] += __shfl_xor_sync(~0u, s[j], o);
                q[j] += __shfl_xor_sync(~0u, q[j], o);
            }
        }
        #pragma unroll
        for (int j = 0; j < 4; j++){
            float m = s[j]*(1.f/64.f);
            float rs = rsqrtf(q[j]*(1.f/64.f) - m*m + 1e-5f);
            float2 o2;
            o2.x = (v[j].x-m)*rs*wv.x + bv.x;
            o2.y = (v[j].y-m)*rs*wv.y + bv.y;
            ((float2*)g_x)[(size_t)(t0+j)*32 + lane] = o2;
        }
    }
}

// ---------------- attention accumulation, grid (16 parts, 128 batch) -------
__global__ void __launch_bounds__(256, 3) k_attn(int fin, float* __restrict__ out_w){
    int p = blockIdx.x, b = blockIdx.y;
    int tid = threadIdx.x, lane = tid & 31, w = tid >> 5;
    __shared__ float xs[CHUNK][68];
    __shared__ u64  ws2[CHUNK][10];
    __shared__ float lgs[CHUNK][12];
    __shared__ u64  qq[16][16];

    {
        int i = tid >> 4, j = tid & 15;
        int s = 4*(j>>3) + ((j>>1)&3);
        int d0 = 4*i + 2*(j&1);
        qq[i][j] = ((const u64*)g_qk)[b*256 + s*32 + (d0>>1)];
    }

    u64 acc[SS]; float dsum[SS];
    #pragma unroll
    for (int s = 0; s < SS; s++){ acc[s] = 0ull; dsum[s] = 0.f; }

    int base = b*NN + p*TOKPB;
    for (int c = 0; c < NCHUNK; c++){
        u64 xr[8];
        const u64* src = (const u64*)(g_x + (size_t)(base + c*CHUNK + 8*w)*64);
        #pragma unroll
        for (int j = 0; j < 8; j++) xr[j] = src[j*32 + lane];
        #pragma unroll
        for (int j = 0; j < 8; j++) *(u64*)&xs[8*w + j][2*lane] = xr[j];
        __syncthreads();

        if (tid < 128){
            int t = tid & 63, g = tid >> 6;
            u64 la0 = 0, la1 = 0, la2 = 0, la3 = 0;
            #pragma unroll
            for (int i = 0; i < 16; i++){
                ulonglong2 xv = *(const ulonglong2*)&xs[t][4*i];
                const ulonglong2* qp = (const ulonglong2*)&qq[i][8*g];
                ulonglong2 q0 = qp[0], q1 = qp[1], q2 = qp[2], q3 = qp[3];
                la0 = ffma2(xv.x, q0.x, la0); la0 = ffma2(xv.y, q0.y, la0);
                la1 = ffma2(xv.x, q1.x, la1); la1 = ffma2(xv.y, q1.y, la1);
                la2 = ffma2(xv.x, q2.x, la2); la2 = ffma2(xv.y, q2.y, la2);
                la3 = ffma2(xv.x, q3.x, la3); la3 = ffma2(xv.y, q3.y, la3);
            }
            float a, bq, l0, l1, l2, l3;
            up2(la0, a, bq); l0 = a + bq;
            up2(la1, a, bq); l1 = a + bq;
            up2(la2, a, bq); l2 = a + bq;
            up2(la3, a, bq); l3 = a + bq;
            *(float4*)&lgs[t][4*g] = make_float4(l0, l1, l2, l3);
        }
        __syncthreads();

        if (tid < 64){
            int t = tid;
            float4 A = *(const float4*)&lgs[t][0];
            float4 Bq = *(const float4*)&lgs[t][4];
            float lg[SS] = {A.x, A.y, A.z, A.w, Bq.x, Bq.y, Bq.z, Bq.w};
            float mx = -1e30f;
            #pragma unroll
            for (int s = 0; s < SS; s++) mx = fmaxf(mx, lg[s]);
            float sum = 0.f;
            #pragma unroll
            for (int s = 0; s < SS; s++){ lg[s] = __expf(lg[s]-mx); sum += lg[s]; }
            float inv = 1.f/sum;
            #pragma unroll
            for (int s = 0; s < SS; s++){
                lg[s] = lg[s]*inv + 1e-8f;
                dsum[s] += lg[s];
            }
            #pragma unroll
            for (int k = 0; k < 4; k++){
                ulonglong2 pr;
                pr.x = pk2(lg[2*k],   lg[2*k]);
                pr.y = pk2(lg[2*k+1], lg[2*k+1]);
                *(ulonglong2*)&ws2[t][2*k] = pr;
            }
            if (fin){
                float4* dst = (float4*)(out_w + (size_t)(base + c*CHUNK + t)*SS);
                dst[0] = make_float4(lg[0], lg[1], lg[2], lg[3]);
                dst[1] = make_float4(lg[4], lg[5], lg[6], lg[7]);
            }
        }
        __syncthreads();

        #pragma unroll
        for (int j = 0; j < 8; j++){
            int n = 8*w + j;
            ulonglong2 w0 = *(const ulonglong2*)&ws2[n][0];
            ulonglong2 w1p = *(const ulonglong2*)&ws2[n][2];
            ulonglong2 w2p = *(const ulonglong2*)&ws2[n][4];
            ulonglong2 w3p = *(const ulonglong2*)&ws2[n][6];
            u64 xv = xr[j];
            acc[0] = ffma2(xv, w0.x,  acc[0]);
            acc[1] = ffma2(xv, w0.y,  acc[1]);
            acc[2] = ffma2(xv, w1p.x, acc[2]);
            acc[3] = ffma2(xv, w1p.y, acc[3]);
            acc[4] = ffma2(xv, w2p.x, acc[4]);
            acc[5] = ffma2(xv, w2p.y, acc[5]);
            acc[6] = ffma2(xv, w3p.x, acc[6]);
            acc[7] = ffma2(xv, w3p.y, acc[7]);
        }
    }
    __syncthreads();

    float* red  = &xs[0][0];
    float* dred = &lgs[0][0];
    #pragma unroll
    for (int s = 0; s < SS; s++){
        float a, bq; up2(acc[s], a, bq);
        red[w*512 + s*64 + 2*lane]   = a;
        red[w*512 + s*64 + 2*lane+1] = bq;
    }
    if (tid < 64){
        #pragma unroll
        for (int s = 0; s < SS; s++) dred[s*64 + tid] = dsum[s];
    }
    __syncthreads();
    #pragma unroll
    for (int k = 0; k < 2; k++){
        int o = tid + k*256;
        float sum = 0.f;
        #pragma unroll
        for (int ww = 0; ww < 8; ww++) sum += red[ww*512 + o];
        g_prep[p*NROW*DD + b*512 + o] = sum;
    }
    if (tid < 8){
        float sum = 0.f;
        #pragma unroll
        for (int t2 = 0; t2 < 64; t2++) sum += dred[tid*64 + t2];
        g_denp[p*NROW + b*SS + tid] = sum;
    }
}

// ---------------- slot update: 256 threads/row ----------------
__global__ void __launch_bounds__(256) k_update(int init, int wout,
    const float* __restrict__ eps, const float* __restrict__ mu,
    const float* __restrict__ lv,
    const float* __restrict__ bih, const float* __restrict__ bhh,
    const float* __restrict__ nrw, const float* __restrict__ nrb,
    const float* __restrict__ b2,  const float* __restrict__ nsw,
    const float* __restrict__ nsb, const float* __restrict__ kw,
    float* __restrict__ out_slots){
    int r = blockIdx.x;
    int tid = threadIdx.x, d = tid & 63, q = tid >> 6;
    int lane = tid & 31, w = tid >> 5;
    __shared__ float av[64], hp[64], tt[64], mm[128];
    __shared__ float pp[4][144];
    __shared__ float pg[6][4][64];
    __shared__ float ps[8], pq2[8];
    float h2;
    if (!init){
        float den = 0.f;
        #pragma unroll
        for (int p = 0; p < NPART; p++) den += g_denp[p*NROW + r];
        if (tid == 0 && wout) g_dent[r] = den;
        float pre = 0.f;
        #pragma unroll
        for (int p = 0; p < NPART; p++) pre += g_prep[p*NROW*DD + r*64 + d];
        if (q == 0){ av[d] = pre/den; hp[d] = g_slots[r*64 + d]; }
        __syncthreads();
        float at = 0.f;
        #pragma unroll
        for (int e0 = 0; e0 < 16; e0++){
            int e = q*16 + e0;
            at += av[e]*g_vwT[e*64 + d];
        }
        pp[q][d] = at;
        __syncthreads();
        at = (pp[0][d]+pp[1][d]) + (pp[2][d]+pp[3][d]);
        __syncthreads();
        if (q == 0) av[d] = at;
        __syncthreads();
        float gr=0.f, gz=0.f, gn=0.f, hr=0.f, hz=0.f, hn=0.f;
        #pragma unroll
        for (int e0 = 0; e0 < 16; e0++){
            int e = q*16 + e0;
            float a = av[e], hpe = hp[e];
            const float* wi = &g_wihT[e*192];
            const float* wh = &g_whhT[e*192];
            gr += a*wi[d];      gz += a*wi[64+d];
            gn += a*wi[128+d];  hr += hpe*wh[d];
            hz += hpe*wh[64+d]; hn += hpe*wh[128+d];
        }
        pg[0][q][d]=gr; pg[1][q][d]=gz; pg[2][q][d]=gn;
        pg[3][q][d]=hr; pg[4][q][d]=hz; pg[5][q][d]=hn;
        __syncthreads();
        gr = bih[d]; gz = bih[64+d]; gn = bih[128+d];
        hr = bhh[d]; hz = bhh[64+d]; hn = bhh[128+d];
        #pragma unroll
        for (int k = 0; k < 4; k++){
            gr += pg[0][k][d]; gz += pg[1][k][d]; gn += pg[2][k][d];
            hr += pg[3][k][d]; hz += pg[4][k][d]; hn += pg[5][k][d];
        }
        float rg = 1.f/(1.f + __expf(-(gr+hr)));
        float zg = 1.f/(1.f + __expf(-(gz+hz)));
        float ng = tanhf(gn + rg*hn);
        float h = (1.f-zg)*ng + zg*hp[d];
        float s = h, qs = h*h;
        #pragma unroll
        for (int o = 16; o; o >>= 1){
            s  += __shfl_xor_sync(~0u, s,  o);
            qs += __shfl_xor_sync(~0u, qs, o);
        }
        if (lane == 0){ ps[w] = s; pq2[w] = qs; }
        __syncthreads();
        int wb = w & ~1;
        s = ps[wb] + ps[wb+1]; qs = pq2[wb] + pq2[wb+1];
        float m = s*(1.f/64.f);
        float rs = rsqrtf(qs*(1.f/64.f) - m*m + 1e-5f);
        float ttv = (h-m)*rs*nrw[d] + nrb[d];
        __syncthreads();
        if (q == 0) tt[d] = ttv;
        __syncthreads();
        int j = tid & 127, hq = tid >> 7;
        float m1 = 0.f;
        #pragma unroll
        for (int e0 = 0; e0 < 32; e0++){
            int e = hq*32 + e0;
            m1 += tt[e]*g_w1T[e*128 + j];
        }
        pp[hq][j] = m1;
        __syncthreads();
        if (hq == 0) mm[j] = fmaxf(pp[0][j] + pp[1][j], 0.f);
        __syncthreads();
        float o2 = 0.f;
        #pragma unroll
        for (int j0 = 0; j0 < 32; j0++){
            int jj = q*32 + j0;
            o2 += mm[jj]*g_w2T[jj*64 + d];
        }
        pp[q][d] = o2;
        __syncthreads();
        h2 = h + b2[d] + (pp[0][d]+pp[1][d]) + (pp[2][d]+pp[3][d]);
        __syncthreads();
    } else {
        h2 = mu[d] + __expf(0.5f*lv[d])*eps[r*64 + d];
    }
    if (q == 0){
        g_slots[r*64 + d] = h2;
        if (wout) out_slots[r*64 + d] = h2;
    }
    float s2 = h2, q2s = h2*h2;
    #pragma unroll
    for (int o = 16; o; o >>= 1){
        s2  += __shfl_xor_sync(~0u, s2,  o);
        q2s += __shfl_xor_sync(~0u, q2s, o);
    }
    if (lane == 0){ ps[w] = s2; pq2[w] = q2s; }
    __syncthreads();
    int wb2 = w & ~1;
    s2 = ps[wb2] + ps[wb2+1]; q2s = pq2[wb2] + pq2[wb2+1];
    float m2 = s2*(1.f/64.f);
    float rs2 = rsqrtf(q2s*(1.f/64.f) - m2*m2 + 1e-5f);
    float ttv2 = (h2-m2)*rs2*nsw[d] + nsb[d];
    __syncthreads();
    if (q == 0) tt[d] = ttv2;
    __syncthreads();
    float qd = 0.f;
    #pragma unroll
    for (int e0 = 0; e0 < 16; e0++){
        int e = q*16 + e0;
        qd += tt[e]*g_qwT[e*64 + d];
    }
    pp[q][d] = qd;
    __syncthreads();
    float qv = (pp[0][d]+pp[1][d]) + (pp[2][d]+pp[3][d]);
    __syncthreads();
    if (q == 0) av[d] = qv;
    __syncthreads();
    float qk = 0.f;
    #pragma unroll
    for (int e0 = 0; e0 < 16; e0++){
        int e = q*16 + e0;
        qk += av[e]*kw[e*64 + d];
    }
    pp[q][d] = qk;
    __syncthreads();
    if (q == 0)
        g_qk[r*64 + d] = 0.125f*((pp[0][d]+pp[1][d]) + (pp[2][d]+pp[3][d]));
}

// ---------------- w = what / denom ----------------
__global__ void __launch_bounds__(256) k_wnorm(float* __restrict__ out_w){
    __shared__ float invd[8];
    int tok = blockIdx.x*256 + threadIdx.x;
    int b = tok >> 12;
    if (threadIdx.x < 8) invd[threadIdx.x] = 1.f/g_dent[b*SS + threadIdx.x];
    __syncthreads();
    float4* pw = (float4*)(out_w + (size_t)tok*SS);
    float4 a = pw[0], c = pw[1];
    a.x *= invd[0]; a.y *= invd[1]; a.z *= invd[2]; a.w *= invd[3];
    c.x *= invd[4]; c.y *= invd[5]; c.z *= invd[6]; c.w *= invd[7];
    pw[0] = a; pw[1] = c;
}

extern "C" void kernel_launch(void* const* d_in, const int* in_sizes, int n_in,
                              void* d_out, int out_size){
    const float* inp = (const float*)d_in[0];
    const float* eps = (const float*)d_in[1];
    const float* mu  = (const float*)d_in[2];
    const float* lv  = (const float*)d_in[3];
    const float* kw  = (const float*)d_in[4];
    const float* vw  = (const float*)d_in[5];
    const float* qw  = (const float*)d_in[6];
    const float* niw = (const float*)d_in[7];
    const float* nib = (const float*)d_in[8];
    const float* nsw = (const float*)d_in[9];
    const float* nsb = (const float*)d_in[10];
    const float* nrw = (const float*)d_in[11];
    const float* nrb = (const float*)d_in[12];
    const float* wih = (const float*)d_in[13];
    const float* whh = (const float*)d_in[14];
    const float* bih = (const float*)d_in[15];
    const float* bhh = (const float*)d_in[16];
    const float* w1  = (const float*)d_in[17];
    const float* w2  = (const float*)d_in[18];
    const float* b2  = (const float*)d_in[19];
    float* out_slots = (float*)d_out;
    float* out_w     = out_slots + NROW*DD;

    k_tr<<<192, 256>>>(vw, wih, whh, w1, w2, qw);
    k_prep<<<2048, 256>>>(inp, niw, nib);
    k_update<<<NROW, 256>>>(1, 0, eps, mu, lv, bih, bhh,
                            nrw, nrb, b2, nsw, nsb, kw, out_slots);
    for (int step = 0; step < 4; step++){
        int fin = (step == 3);
        k_attn<<<dim3(NPART, BB), 256>>>(fin, out_w);
        k_update<<<NROW, 256>>>(0, fin, eps, mu, lv, bih, bhh,
                                nrw, nrb, b2, nsw, nsb, kw, out_slots);
    }
    k_wnorm<<<NTOK/256, 256>>>(out_w);
}